// round 1
// baseline (speedup 1.0000x reference)
#include <cuda_runtime.h>
#include <cstdint>

#define B_ 16
#define A_ 5
#define C_ 20
#define HF 19
#define WF 19
#define S_ 361           // 19*19
#define N_ 1805          // A_*S_
#define BN 28880         // B_*N_
#define PROB_ELEMS 577600  // B_*N_*C_
#define NW 57            // ceil(1805/32)
#define MROW 64          // padded words per mask row (uint2 x 32)
#define NTILE 1653       // 57*58/2 upper-triangle tiles

__constant__ float c_biases[10] = {1.08f, 1.19f, 3.42f, 4.41f, 6.63f,
                                   11.38f, 9.42f, 5.11f, 16.62f, 10.52f};

// scratch (zero-initialized at module load; padding words of g_mask stay 0)
__device__ float g_scores[PROB_ELEMS];                   // [b][c][n]
__device__ float g_x1[BN], g_y1[BN], g_x2[BN], g_y2[BN], g_area[BN];
__device__ unsigned g_mask[(size_t)B_ * N_ * MROW];      // [b][i][word]
__device__ unsigned long long g_order[(size_t)B_ * C_ * N_];

// ---------------------------------------------------------------------------
// K1: decode boxes + scores
// ---------------------------------------------------------------------------
__global__ __launch_bounds__(128) void k_decode(const float* __restrict__ x,
                                                const float* __restrict__ iminfo,
                                                float* __restrict__ out) {
    int t = blockIdx.x * blockDim.x + threadIdx.x;
    if (t >= BN) return;
    int b = t / N_, n = t - b * N_;
    int a = n / S_, s = n - a * S_;
    int hy = s / WF, wx = s - hy * WF;
    const float* p = x + (size_t)b * (125 * S_) + s;

    float tx = p[(2 * a) * S_];
    float ty = p[(2 * a + 1) * S_];
    float tw = p[(10 + 2 * a) * S_];
    float th = p[(11 + 2 * a) * S_];
    float to = p[(20 + a) * S_];

    float sx = 1.0f / (1.0f + expf(-tx));
    float sy = 1.0f / (1.0f + expf(-ty));
    float obj = 1.0f / (1.0f + expf(-to));

    float cf[C_];
    float mx = -1e30f;
#pragma unroll
    for (int c = 0; c < C_; c++) {
        cf[c] = p[(25 + a * C_ + c) * S_];
        mx = fmaxf(mx, cf[c]);
    }
    float sum = 0.0f;
#pragma unroll
    for (int c = 0; c < C_; c++) {
        cf[c] = expf(cf[c] - mx);
        sum += cf[c];
    }
    float osc = obj / sum;

    float imh = iminfo[2 * b + 0];
    float imw = iminfo[2 * b + 1];

    float bx = (sx + (float)wx) / 19.0f * imw;
    float by = (sy + (float)hy) / 19.0f * imh;
    float bw = expf(tw) * c_biases[2 * a] / 19.0f * imw;
    float bh = expf(th) * c_biases[2 * a + 1] / 19.0f * imh;

    reinterpret_cast<float4*>(out + PROB_ELEMS)[t] = make_float4(bx, by, bw, bh);

    float hw = bw * 0.5f, hh = bh * 0.5f;
    g_x1[t] = bx - hw;
    g_x2[t] = bx + hw;
    g_y1[t] = by - hh;
    g_y2[t] = by + hh;
    g_area[t] = bw * bh;

#pragma unroll
    for (int c = 0; c < C_; c++)
        g_scores[((size_t)b * C_ + c) * N_ + n] = cf[c] * osc;
}

// ---------------------------------------------------------------------------
// K2: suppression bitmask, one warp per 32x32 tile, upper triangle + ballot
// ---------------------------------------------------------------------------
__global__ __launch_bounds__(256) void k_mask() {
    int b = blockIdx.x;
    int warp = blockIdx.y * (blockDim.x >> 5) + (threadIdx.x >> 5);
    if (warp >= NTILE) return;
    int lane = threadIdx.x & 31;

    // map warp -> (rb, w) in upper triangle (w >= rb)
    int rb = 0, rem = warp;
    while (rem >= NW - rb) { rem -= NW - rb; rb++; }
    int w = rb + rem;

    int i = rb * 32 + lane;
    int gi = b * N_ + min(i, N_ - 1);
    float ix1 = g_x1[gi], iy1 = g_y1[gi], ix2 = g_x2[gi], iy2 = g_y2[gi];
    float ki = fmaf(0.45f, g_area[gi], 4.5e-10f);

    int jl = w * 32 + lane;
    int gj = b * N_ + min(jl, N_ - 1);
    float cx1 = g_x1[gj], cy1 = g_y1[gj], cx2 = g_x2[gj], cy2 = g_y2[gj];
    float ca = g_area[gj];

    unsigned bits = 0u, tbits = 0u;
    int jbase = w * 32;
#pragma unroll 8
    for (int jj = 0; jj < 32; jj++) {
        float jx1 = __shfl_sync(0xFFFFFFFFu, cx1, jj);
        float jy1 = __shfl_sync(0xFFFFFFFFu, cy1, jj);
        float jx2 = __shfl_sync(0xFFFFFFFFu, cx2, jj);
        float jy2 = __shfl_sync(0xFFFFFFFFu, cy2, jj);
        float ja  = __shfl_sync(0xFFFFFFFFu, ca, jj);
        float iw = fmaxf(fminf(ix2, jx2) - fmaxf(ix1, jx1), 0.0f);
        float ih = fmaxf(fminf(iy2, jy2) - fmaxf(iy1, jy1), 0.0f);
        float inter = iw * ih;
        // inter/(ai+aj-inter+1e-9) > 0.45  <=>  inter*1.45 > 0.45*(ai+aj+1e-9)
        bool pred = (inter * 1.45f > fmaf(0.45f, ja, ki)) && (i != jbase + jj);
        unsigned bal = __ballot_sync(0xFFFFFFFFu, pred);
        bits |= pred ? (1u << jj) : 0u;
        if (lane == jj) tbits = bal;
    }
    if (i < N_) g_mask[(size_t)(b * N_ + i) * MROW + w] = bits;
    if (w != rb && jl < N_) g_mask[(size_t)(b * N_ + jl) * MROW + rb] = tbits;
}

// ---------------------------------------------------------------------------
// K3: bitonic sort (descending) of 2048 packed keys per (b,c)
// key = (score_bits << 32) | (2047 - idx)   -> stable-tie matches argsort
// ---------------------------------------------------------------------------
__global__ __launch_bounds__(1024) void k_sort() {
    __shared__ unsigned long long sm[2048];
    int p = blockIdx.x;           // 0..319 = b*C + c
    int tid = threadIdx.x;
    const float* sc = g_scores + (size_t)p * N_;

#pragma unroll
    for (int q = 0; q < 2; q++) {
        int t = tid + q * 1024;
        unsigned long long key = 0ull;
        if (t < N_)
            key = ((unsigned long long)__float_as_uint(sc[t]) << 32) |
                  (unsigned long long)(2047u - (unsigned)t);
        sm[t] = key;
    }
    __syncthreads();

    for (int k = 2; k <= 2048; k <<= 1) {
        for (int j = k >> 1; j > 0; j >>= 1) {
            int i = ((tid & ~(j - 1)) << 1) | (tid & (j - 1));
            int pi = i | j;
            bool desc = ((i & k) == 0);
            unsigned long long a = sm[i], bb = sm[pi];
            if ((a < bb) == desc) { sm[i] = bb; sm[pi] = a; }
            __syncthreads();
        }
    }

    unsigned long long* op = g_order + (size_t)p * N_;
#pragma unroll
    for (int q = 0; q < 2; q++) {
        int t = tid + q * 1024;
        if (t < N_) op[t] = sm[t];
    }
}

// ---------------------------------------------------------------------------
// K4: greedy NMS, one warp per (b,c); keep bitmask 2 words/lane in registers.
// Mask rows prefetched 4 iterations ahead, keys 8 ahead.
// ---------------------------------------------------------------------------
__global__ __launch_bounds__(32) void k_nms(float* __restrict__ out) {
    int p = blockIdx.x;                 // 0..319
    int b = p / C_, c = p - b * C_;
    int lane = threadIdx.x;

    const unsigned long long* ord = g_order + (size_t)p * N_;
    const uint2* mrow = reinterpret_cast<const uint2*>(g_mask) + (size_t)b * N_ * 32;
    float* op = out + (size_t)b * N_ * C_ + c;

    unsigned keep0 = 0xFFFFFFFFu, keep1 = 0xFFFFFFFFu;

    const int KP = 8, MP = 4;
    unsigned long long kq[KP];
    uint2 mq[MP];
#pragma unroll
    for (int q = 0; q < KP; q++) kq[q] = ord[q];
#pragma unroll
    for (int q = 0; q < MP; q++) {
        unsigned idx = 2047u - (unsigned)kq[q];
        mq[q] = mrow[idx * 32u + lane];
    }

#pragma unroll 4
    for (int i = 0; i < N_; i++) {
        unsigned long long key = kq[i & (KP - 1)];
        uint2 m = mq[i & (MP - 1)];

        int ik = i + KP;
        kq[i & (KP - 1)] = (ik < N_) ? ord[ik] : 0ull;
        int im = i + MP;
        if (im < N_) {
            unsigned nidx = 2047u - (unsigned)kq[im & (KP - 1)];
            mq[i & (MP - 1)] = mrow[nidx * 32u + lane];
        }

        unsigned idx = 2047u - (unsigned)key;
        unsigned wq = idx >> 5;
        unsigned v0 = __shfl_sync(0xFFFFFFFFu, keep0, wq >> 1);
        unsigned v1 = __shfl_sync(0xFFFFFFFFu, keep1, wq >> 1);
        unsigned wv = (wq & 1u) ? v1 : v0;
        unsigned kept = (wv >> (idx & 31u)) & 1u;

        if (lane == 0) {
            float sc = __uint_as_float((unsigned)(key >> 32));
            op[(size_t)idx * C_] = kept ? sc : 0.0f;
        }
        if (kept) { keep0 &= ~m.x; keep1 &= ~m.y; }
    }
}

// ---------------------------------------------------------------------------
extern "C" void kernel_launch(void* const* d_in, const int* in_sizes, int n_in,
                              void* d_out, int out_size) {
    const float* x = (const float*)d_in[0];
    const float* iminfo = (const float*)d_in[1];
    float* out = (float*)d_out;

    k_decode<<<(BN + 127) / 128, 128>>>(x, iminfo, out);

    dim3 gm(B_, (NTILE + 7) / 8);
    k_mask<<<gm, 256>>>();

    k_sort<<<B_ * C_, 1024>>>();

    k_nms<<<B_ * C_, 32>>>(out);
}

// round 2
// speedup vs baseline: 2.9910x; 2.9910x over previous
#include <cuda_runtime.h>
#include <cstdint>

#define B_ 16
#define A_ 5
#define C_ 20
#define HF 19
#define WF 19
#define S_ 361           // 19*19
#define N_ 1805          // A_*S_
#define BN 28880         // B_*N_
#define PROB_ELEMS 577600  // B_*N_*C_
#define NW 57            // ceil(1805/32)
#define MROW 64          // padded words per mask row (uint2 x 32)
#define NTILE 1653       // 57*58/2 upper-triangle tiles

__constant__ float c_biases[10] = {1.08f, 1.19f, 3.42f, 4.41f, 6.63f,
                                   11.38f, 9.42f, 5.11f, 16.62f, 10.52f};

// scratch (zero-initialized at module load; padding words of g_mask stay 0)
__device__ float g_scores[PROB_ELEMS];                   // [b][c][n]
__device__ float g_x1[BN], g_y1[BN], g_x2[BN], g_y2[BN], g_area[BN];
__device__ unsigned g_mask[(size_t)B_ * N_ * MROW];      // [b][i][word]
__device__ unsigned long long g_order[(size_t)B_ * C_ * N_];

// ---------------------------------------------------------------------------
// K1: decode boxes + scores
// ---------------------------------------------------------------------------
__global__ __launch_bounds__(128) void k_decode(const float* __restrict__ x,
                                                const float* __restrict__ iminfo,
                                                float* __restrict__ out) {
    int t = blockIdx.x * blockDim.x + threadIdx.x;
    if (t >= BN) return;
    int b = t / N_, n = t - b * N_;
    int a = n / S_, s = n - a * S_;
    int hy = s / WF, wx = s - hy * WF;
    const float* p = x + (size_t)b * (125 * S_) + s;

    float tx = p[(2 * a) * S_];
    float ty = p[(2 * a + 1) * S_];
    float tw = p[(10 + 2 * a) * S_];
    float th = p[(11 + 2 * a) * S_];
    float to = p[(20 + a) * S_];

    float sx = 1.0f / (1.0f + expf(-tx));
    float sy = 1.0f / (1.0f + expf(-ty));
    float obj = 1.0f / (1.0f + expf(-to));

    float cf[C_];
    float mx = -1e30f;
#pragma unroll
    for (int c = 0; c < C_; c++) {
        cf[c] = p[(25 + a * C_ + c) * S_];
        mx = fmaxf(mx, cf[c]);
    }
    float sum = 0.0f;
#pragma unroll
    for (int c = 0; c < C_; c++) {
        cf[c] = expf(cf[c] - mx);
        sum += cf[c];
    }
    float osc = obj / sum;

    float imh = iminfo[2 * b + 0];
    float imw = iminfo[2 * b + 1];

    float bx = (sx + (float)wx) / 19.0f * imw;
    float by = (sy + (float)hy) / 19.0f * imh;
    float bw = expf(tw) * c_biases[2 * a] / 19.0f * imw;
    float bh = expf(th) * c_biases[2 * a + 1] / 19.0f * imh;

    reinterpret_cast<float4*>(out + PROB_ELEMS)[t] = make_float4(bx, by, bw, bh);

    float hw = bw * 0.5f, hh = bh * 0.5f;
    g_x1[t] = bx - hw;
    g_x2[t] = bx + hw;
    g_y1[t] = by - hh;
    g_y2[t] = by + hh;
    g_area[t] = bw * bh;

#pragma unroll
    for (int c = 0; c < C_; c++)
        g_scores[((size_t)b * C_ + c) * N_ + n] = cf[c] * osc;
}

// ---------------------------------------------------------------------------
// K2: suppression bitmask, one warp per 32x32 tile, upper triangle + ballot
// ---------------------------------------------------------------------------
__global__ __launch_bounds__(256) void k_mask() {
    int b = blockIdx.x;
    int warp = blockIdx.y * (blockDim.x >> 5) + (threadIdx.x >> 5);
    if (warp >= NTILE) return;
    int lane = threadIdx.x & 31;

    // map warp -> (rb, w) in upper triangle (w >= rb)
    int rb = 0, rem = warp;
    while (rem >= NW - rb) { rem -= NW - rb; rb++; }
    int w = rb + rem;

    int i = rb * 32 + lane;
    int gi = b * N_ + min(i, N_ - 1);
    float ix1 = g_x1[gi], iy1 = g_y1[gi], ix2 = g_x2[gi], iy2 = g_y2[gi];
    float ki = fmaf(0.45f, g_area[gi], 4.5e-10f);

    int jl = w * 32 + lane;
    int gj = b * N_ + min(jl, N_ - 1);
    float cx1 = g_x1[gj], cy1 = g_y1[gj], cx2 = g_x2[gj], cy2 = g_y2[gj];
    float ca = g_area[gj];

    unsigned bits = 0u, tbits = 0u;
    int jbase = w * 32;
#pragma unroll 8
    for (int jj = 0; jj < 32; jj++) {
        float jx1 = __shfl_sync(0xFFFFFFFFu, cx1, jj);
        float jy1 = __shfl_sync(0xFFFFFFFFu, cy1, jj);
        float jx2 = __shfl_sync(0xFFFFFFFFu, cx2, jj);
        float jy2 = __shfl_sync(0xFFFFFFFFu, cy2, jj);
        float ja  = __shfl_sync(0xFFFFFFFFu, ca, jj);
        float iw = fmaxf(fminf(ix2, jx2) - fmaxf(ix1, jx1), 0.0f);
        float ih = fmaxf(fminf(iy2, jy2) - fmaxf(iy1, jy1), 0.0f);
        float inter = iw * ih;
        // inter/(ai+aj-inter+1e-9) > 0.45  <=>  inter*1.45 > 0.45*(ai+aj+1e-9)
        bool pred = (inter * 1.45f > fmaf(0.45f, ja, ki)) && (i != jbase + jj);
        unsigned bal = __ballot_sync(0xFFFFFFFFu, pred);
        bits |= pred ? (1u << jj) : 0u;
        if (lane == jj) tbits = bal;
    }
    if (i < N_) g_mask[(size_t)(b * N_ + i) * MROW + w] = bits;
    if (w != rb && jl < N_) g_mask[(size_t)(b * N_ + jl) * MROW + rb] = tbits;
}

// ---------------------------------------------------------------------------
// K3: bitonic sort (descending) of 2048 packed keys per (b,c)
// key = (score_bits << 32) | (2047 - idx)   -> stable-tie matches argsort
// ---------------------------------------------------------------------------
__global__ __launch_bounds__(1024) void k_sort() {
    __shared__ unsigned long long sm[2048];
    int p = blockIdx.x;           // 0..319 = b*C + c
    int tid = threadIdx.x;
    const float* sc = g_scores + (size_t)p * N_;

#pragma unroll
    for (int q = 0; q < 2; q++) {
        int t = tid + q * 1024;
        unsigned long long key = 0ull;
        if (t < N_)
            key = ((unsigned long long)__float_as_uint(sc[t]) << 32) |
                  (unsigned long long)(2047u - (unsigned)t);
        sm[t] = key;
    }
    __syncthreads();

    for (int k = 2; k <= 2048; k <<= 1) {
        for (int j = k >> 1; j > 0; j >>= 1) {
            int i = ((tid & ~(j - 1)) << 1) | (tid & (j - 1));
            int pi = i | j;
            bool desc = ((i & k) == 0);
            unsigned long long a = sm[i], bb = sm[pi];
            if ((a < bb) == desc) { sm[i] = bb; sm[pi] = a; }
            __syncthreads();
        }
    }

    unsigned long long* op = g_order + (size_t)p * N_;
#pragma unroll
    for (int q = 0; q < 2; q++) {
        int t = tid + q * 1024;
        if (t < N_) op[t] = sm[t];
    }
}

// ---------------------------------------------------------------------------
// K4: greedy NMS, one warp per (b,c); keep bitmask 2 words/lane in registers.
// Fully unrolled x16 software pipeline: keys 16 ahead, mask rows 8 ahead
// (all queue indices compile-time -> no local-memory spill).
// Branchless keep-update via sign-extend mask (no pred-as-guard on the chain).
// ---------------------------------------------------------------------------
__global__ __launch_bounds__(32) void k_nms(float* __restrict__ out) {
    int p = blockIdx.x;                 // 0..319
    int b = p / C_, c = p - b * C_;
    int lane = threadIdx.x;

    const unsigned long long* __restrict__ ord = g_order + (size_t)p * N_;
    const uint2* __restrict__ mrow =
        reinterpret_cast<const uint2*>(g_mask) + (size_t)b * N_ * 32;
    float* __restrict__ op = out + (size_t)b * N_ * C_ + c;

    // lane l holds keep words 2l (keep0) and 2l+1 (keep1)
    unsigned keep0 = 0xFFFFFFFFu, keep1 = 0xFFFFFFFFu;

    unsigned long long kq[16];
    uint2 mq[8];
#pragma unroll
    for (int q = 0; q < 16; q++) kq[q] = ord[q];
#pragma unroll
    for (int q = 0; q < 8; q++) {
        unsigned idx = min(2047u - (unsigned)kq[q], (unsigned)(N_ - 1));
        mq[q] = mrow[idx * 32u + lane];
    }

    for (int i0 = 0; i0 < 1808; i0 += 16) {      // 113 blocks of 16 (pad past N_)
#pragma unroll
        for (int j = 0; j < 16; j++) {
            int i = i0 + j;
            unsigned long long key = kq[j];
            uint2 m = mq[j & 7];

            // refill key queue: key for iteration i+16
            int ik = i + 16;
            kq[j] = (ik < N_) ? ord[ik] : 0ull;

            // refill mask queue: mask row for iteration i+8
            // (its key sits in slot (j+8)&15, loaded 8 iterations ago)
            {
                unsigned nidx =
                    min(2047u - (unsigned)kq[(j + 8) & 15], (unsigned)(N_ - 1));
                mq[j & 7] = mrow[nidx * 32u + lane];
            }

            unsigned idx = 2047u - (unsigned)key;   // uniform across warp
            unsigned wq = idx >> 5;                  // keep word index 0..63
            unsigned sh = 31u - (idx & 31u);         // off-chain

            unsigned v0 = __shfl_sync(0xFFFFFFFFu, keep0, wq >> 1);
            unsigned v1 = __shfl_sync(0xFFFFFFFFu, keep1, wq >> 1);
            unsigned wv = (wq & 1u) ? v1 : v0;
            // all-ones if this box is still kept, else 0 (sign-extend of bit)
            unsigned msk = (unsigned)((int)(wv << sh) >> 31);

            if (lane == 0 && i < N_) {
                float sc = __uint_as_float((unsigned)(key >> 32));
                op[(size_t)idx * C_] = (msk & 1u) ? sc : 0.0f;
            }
            // single LOP3 per word: keep &= ~(m & msk)
            keep0 &= ~(m.x & msk);
            keep1 &= ~(m.y & msk);
        }
    }
}

// ---------------------------------------------------------------------------
extern "C" void kernel_launch(void* const* d_in, const int* in_sizes, int n_in,
                              void* d_out, int out_size) {
    const float* x = (const float*)d_in[0];
    const float* iminfo = (const float*)d_in[1];
    float* out = (float*)d_out;

    k_decode<<<(BN + 127) / 128, 128>>>(x, iminfo, out);

    dim3 gm(B_, (NTILE + 7) / 8);
    k_mask<<<gm, 256>>>();

    k_sort<<<B_ * C_, 1024>>>();

    k_nms<<<B_ * C_, 32>>>(out);
}

// round 3
// speedup vs baseline: 3.3648x; 1.1250x over previous
#include <cuda_runtime.h>
#include <cstdint>

#define B_ 16
#define A_ 5
#define C_ 20
#define HF 19
#define WF 19
#define S_ 361           // 19*19
#define N_ 1805          // A_*S_
#define BN 28880         // B_*N_
#define PROB_ELEMS 577600  // B_*N_*C_
#define NW 57            // ceil(1805/32)
#define MROW 64          // padded words per mask row (uint2 x 32)
#define NTILE 1653       // 57*58/2 upper-triangle tiles

__constant__ float c_biases[10] = {1.08f, 1.19f, 3.42f, 4.41f, 6.63f,
                                   11.38f, 9.42f, 5.11f, 16.62f, 10.52f};

// scratch (zero-initialized at module load; padding words of g_mask stay 0
// forever: k_mask only ever writes words 0..56 of each row)
__device__ float g_scores[PROB_ELEMS];                   // [b][c][n]
__device__ float g_x1[BN], g_y1[BN], g_x2[BN], g_y2[BN], g_area[BN];
__device__ unsigned g_mask[(size_t)B_ * N_ * MROW];      // [b][i][word]
__device__ unsigned long long g_order[(size_t)B_ * C_ * N_];

// ---------------------------------------------------------------------------
// K1: decode boxes + scores
// ---------------------------------------------------------------------------
__global__ __launch_bounds__(128) void k_decode(const float* __restrict__ x,
                                                const float* __restrict__ iminfo,
                                                float* __restrict__ out) {
    int t = blockIdx.x * blockDim.x + threadIdx.x;
    if (t >= BN) return;
    int b = t / N_, n = t - b * N_;
    int a = n / S_, s = n - a * S_;
    int hy = s / WF, wx = s - hy * WF;
    const float* p = x + (size_t)b * (125 * S_) + s;

    float tx = p[(2 * a) * S_];
    float ty = p[(2 * a + 1) * S_];
    float tw = p[(10 + 2 * a) * S_];
    float th = p[(11 + 2 * a) * S_];
    float to = p[(20 + a) * S_];

    float sx = 1.0f / (1.0f + expf(-tx));
    float sy = 1.0f / (1.0f + expf(-ty));
    float obj = 1.0f / (1.0f + expf(-to));

    float cf[C_];
    float mx = -1e30f;
#pragma unroll
    for (int c = 0; c < C_; c++) {
        cf[c] = p[(25 + a * C_ + c) * S_];
        mx = fmaxf(mx, cf[c]);
    }
    float sum = 0.0f;
#pragma unroll
    for (int c = 0; c < C_; c++) {
        cf[c] = expf(cf[c] - mx);
        sum += cf[c];
    }
    float osc = obj / sum;

    float imh = iminfo[2 * b + 0];
    float imw = iminfo[2 * b + 1];

    float bx = (sx + (float)wx) / 19.0f * imw;
    float by = (sy + (float)hy) / 19.0f * imh;
    float bw = expf(tw) * c_biases[2 * a] / 19.0f * imw;
    float bh = expf(th) * c_biases[2 * a + 1] / 19.0f * imh;

    reinterpret_cast<float4*>(out + PROB_ELEMS)[t] = make_float4(bx, by, bw, bh);

    float hw = bw * 0.5f, hh = bh * 0.5f;
    g_x1[t] = bx - hw;
    g_x2[t] = bx + hw;
    g_y1[t] = by - hh;
    g_y2[t] = by + hh;
    g_area[t] = bw * bh;

#pragma unroll
    for (int c = 0; c < C_; c++)
        g_scores[((size_t)b * C_ + c) * N_ + n] = cf[c] * osc;
}

// ---------------------------------------------------------------------------
// K2: suppression bitmask, one warp per 32x32 tile, upper triangle + ballot
// ---------------------------------------------------------------------------
__global__ __launch_bounds__(256) void k_mask() {
    int b = blockIdx.x;
    int warp = blockIdx.y * (blockDim.x >> 5) + (threadIdx.x >> 5);
    if (warp >= NTILE) return;
    int lane = threadIdx.x & 31;

    // map warp -> (rb, w) in upper triangle (w >= rb)
    int rb = 0, rem = warp;
    while (rem >= NW - rb) { rem -= NW - rb; rb++; }
    int w = rb + rem;

    int i = rb * 32 + lane;
    int gi = b * N_ + min(i, N_ - 1);
    float ix1 = g_x1[gi], iy1 = g_y1[gi], ix2 = g_x2[gi], iy2 = g_y2[gi];
    float ki = fmaf(0.45f, g_area[gi], 4.5e-10f);

    int jl = w * 32 + lane;
    int gj = b * N_ + min(jl, N_ - 1);
    float cx1 = g_x1[gj], cy1 = g_y1[gj], cx2 = g_x2[gj], cy2 = g_y2[gj];
    float ca = g_area[gj];

    unsigned bits = 0u, tbits = 0u;
    int jbase = w * 32;
#pragma unroll 8
    for (int jj = 0; jj < 32; jj++) {
        float jx1 = __shfl_sync(0xFFFFFFFFu, cx1, jj);
        float jy1 = __shfl_sync(0xFFFFFFFFu, cy1, jj);
        float jx2 = __shfl_sync(0xFFFFFFFFu, cx2, jj);
        float jy2 = __shfl_sync(0xFFFFFFFFu, cy2, jj);
        float ja  = __shfl_sync(0xFFFFFFFFu, ca, jj);
        float iw = fmaxf(fminf(ix2, jx2) - fmaxf(ix1, jx1), 0.0f);
        float ih = fmaxf(fminf(iy2, jy2) - fmaxf(iy1, jy1), 0.0f);
        float inter = iw * ih;
        // inter/(ai+aj-inter+1e-9) > 0.45  <=>  inter*1.45 > 0.45*(ai+aj+1e-9)
        bool pred = (inter * 1.45f > fmaf(0.45f, ja, ki)) && (i != jbase + jj);
        unsigned bal = __ballot_sync(0xFFFFFFFFu, pred);
        bits |= pred ? (1u << jj) : 0u;
        if (lane == jj) tbits = bal;
    }
    if (i < N_) g_mask[(size_t)(b * N_ + i) * MROW + w] = bits;
    if (w != rb && jl < N_) g_mask[(size_t)(b * N_ + jl) * MROW + rb] = tbits;
}

// ---------------------------------------------------------------------------
// K3: bitonic sort (descending) of 2048 packed keys per (b,c)
// key = (score_bits << 32) | (2047 - idx)   -> stable-tie matches argsort
// ---------------------------------------------------------------------------
__global__ __launch_bounds__(1024) void k_sort() {
    __shared__ unsigned long long sm[2048];
    int p = blockIdx.x;           // 0..319 = b*C + c
    int tid = threadIdx.x;
    const float* sc = g_scores + (size_t)p * N_;

#pragma unroll
    for (int q = 0; q < 2; q++) {
        int t = tid + q * 1024;
        unsigned long long key = 0ull;
        if (t < N_)
            key = ((unsigned long long)__float_as_uint(sc[t]) << 32) |
                  (unsigned long long)(2047u - (unsigned)t);
        sm[t] = key;
    }
    __syncthreads();

    for (int k = 2; k <= 2048; k <<= 1) {
        for (int j = k >> 1; j > 0; j >>= 1) {
            int i = ((tid & ~(j - 1)) << 1) | (tid & (j - 1));
            int pi = i | j;
            bool desc = ((i & k) == 0);
            unsigned long long a = sm[i], bb = sm[pi];
            if ((a < bb) == desc) { sm[i] = bb; sm[pi] = a; }
            __syncthreads();
        }
    }

    unsigned long long* op = g_order + (size_t)p * N_;
#pragma unroll
    for (int q = 0; q < 2; q++) {
        int t = tid + q * 1024;
        if (t < N_) op[t] = sm[t];
    }
}

// ---------------------------------------------------------------------------
// K4: greedy NMS, chunked 32-at-a-time.
// Per chunk: all cross-lane work (mask loads, suppression columns via ballot,
// keep-bit gather) is off the serial chain; the greedy recurrence collapses to
// a 32-step scalar loop on a uniform 'alive' word: 12 cy/step.
// Global keep bitmask: lane l owns words 2l, 2l+1 (registers keepX/keepY).
// ---------------------------------------------------------------------------
__global__ __launch_bounds__(32) void k_nms(float* __restrict__ out) {
    int p = blockIdx.x;                 // 0..319
    int b = p / C_, c = p - b * C_;
    int lane = threadIdx.x;

    const unsigned long long* __restrict__ ord = g_order + (size_t)p * N_;
    const unsigned* __restrict__ mbase = g_mask + (size_t)b * N_ * MROW;
    const uint2* __restrict__ mrow2 = reinterpret_cast<const uint2*>(mbase);
    float* __restrict__ op = out + (size_t)b * N_ * C_ + c;

    unsigned keepX = 0xFFFFFFFFu, keepY = 0xFFFFFFFFu;

    // per-lane key for chunk 0 (rank = lane)
    unsigned long long key = ord[lane];

    for (int ch = 0; ch < 57; ch++) {
        int rank = ch * 32 + lane;
        unsigned valid = (rank < N_) ? 1u : 0u;
        unsigned idxj = 2047u - (unsigned)key;          // per-lane box index
        unsigned wqj = idxj >> 5;                       // keep/mask word index
        unsigned bmask = 1u << (idxj & 31u);
        float scorej = __uint_as_float((unsigned)(key >> 32));
        unsigned kl = (unsigned)key;                    // low 32 for broadcast

        // prefetch next chunk's per-lane key (predicated, off-chain)
        int nrank = rank + 32;
        unsigned long long nkey = (nrank < N_) ? ord[nrank] : 0ull;

        // broadcast member indices; issue all mask loads for this chunk:
        //   m[i] : member i's row distributed 2 words/lane (for keep update)
        //   q[i] : member i's row word wqj (for suppression-column extraction)
        unsigned q[32];
        uint2 m[32];
#pragma unroll
        for (int i = 0; i < 32; i++) {
            unsigned kli = __shfl_sync(0xFFFFFFFFu, kl, i);
            unsigned idxi = min(2047u - kli, (unsigned)(N_ - 1));
            m[i] = mrow2[idxi * 32u + lane];
            q[i] = mbase[(size_t)idxi * 64u + wqj];
        }

        // gather this chunk's keep bits -> uniform 'alive' word
        unsigned vx = __shfl_sync(0xFFFFFFFFu, keepX, wqj >> 1);
        unsigned vy = __shfl_sync(0xFFFFFFFFu, keepY, wqj >> 1);
        unsigned wv = (wqj & 1u) ? vy : vx;
        unsigned alive =
            __ballot_sync(0xFFFFFFFFu, (wv & bmask) != 0u && valid);

        // suppression columns: sup[i] bit j = member i's mask has bit idx_j,
        // restricted to later-ranked members (bits > i)
        unsigned sup[32];
#pragma unroll
        for (int i = 0; i < 32; i++) {
            unsigned bal = __ballot_sync(0xFFFFFFFFu, (q[i] & bmask) != 0u);
            sup[i] = bal & (0xFFFFFFFEu << i);
        }

        // serial greedy recurrence (uniform scalar, 12 cy/step) + fused
        // row-combine for the global keep update (off-chain LOP3s)
        unsigned cmbx = 0u, cmby = 0u;
#pragma unroll
        for (int i = 0; i < 32; i++) {
            unsigned msk = (unsigned)((int)(alive << (31 - i)) >> 31);
            alive &= ~(sup[i] & msk);
            cmbx |= m[i].x & msk;
            cmby |= m[i].y & msk;
        }
        keepX &= ~cmbx;
        keepY &= ~cmby;

        // per-lane predicated store (no divergent branch): lane j writes
        // member j's score (kept bits were preserved by the >i sup masking)
        float val = ((alive >> lane) & 1u) ? scorej : 0.0f;
        float* addr = op + (size_t)idxj * C_;
        asm volatile(
            "{ .reg .pred p; setp.ne.u32 p, %0, 0;\n"
            "  @p st.global.f32 [%1], %2; }"
            :: "r"(valid), "l"(addr), "f"(val) : "memory");

        key = nkey;
    }
}

// ---------------------------------------------------------------------------
extern "C" void kernel_launch(void* const* d_in, const int* in_sizes, int n_in,
                              void* d_out, int out_size) {
    const float* x = (const float*)d_in[0];
    const float* iminfo = (const float*)d_in[1];
    float* out = (float*)d_out;

    k_decode<<<(BN + 127) / 128, 128>>>(x, iminfo, out);

    dim3 gm(B_, (NTILE + 7) / 8);
    k_mask<<<gm, 256>>>();

    k_sort<<<B_ * C_, 1024>>>();

    k_nms<<<B_ * C_, 32>>>(out);
}

// round 4
// speedup vs baseline: 4.0725x; 1.2103x over previous
#include <cuda_runtime.h>
#include <cstdint>

#define B_ 16
#define A_ 5
#define C_ 20
#define HF 19
#define WF 19
#define S_ 361           // 19*19
#define N_ 1805          // A_*S_
#define BN 28880         // B_*N_
#define PROB_ELEMS 577600  // B_*N_*C_
#define NW 57            // ceil(1805/32)
#define MROW 64          // padded words per mask row (uint2 x 32)
#define NTILE 1653       // 57*58/2 upper-triangle tiles

__constant__ float c_biases[10] = {1.08f, 1.19f, 3.42f, 4.41f, 6.63f,
                                   11.38f, 9.42f, 5.11f, 16.62f, 10.52f};

// scratch (zero-initialized at module load; padding words of g_mask stay 0
// forever: k_mask only ever writes words 0..56 of each row)
__device__ float g_scores[PROB_ELEMS];                   // [b][c][n]
__device__ float g_x1[BN], g_y1[BN], g_x2[BN], g_y2[BN], g_area[BN];
__device__ unsigned g_mask[(size_t)B_ * N_ * MROW];      // [b][i][word]
__device__ unsigned long long g_order[(size_t)B_ * C_ * N_];

// ---------------------------------------------------------------------------
// K1: decode boxes + scores
// ---------------------------------------------------------------------------
__global__ __launch_bounds__(128) void k_decode(const float* __restrict__ x,
                                                const float* __restrict__ iminfo,
                                                float* __restrict__ out) {
    int t = blockIdx.x * blockDim.x + threadIdx.x;
    if (t >= BN) return;
    int b = t / N_, n = t - b * N_;
    int a = n / S_, s = n - a * S_;
    int hy = s / WF, wx = s - hy * WF;
    const float* p = x + (size_t)b * (125 * S_) + s;

    float tx = p[(2 * a) * S_];
    float ty = p[(2 * a + 1) * S_];
    float tw = p[(10 + 2 * a) * S_];
    float th = p[(11 + 2 * a) * S_];
    float to = p[(20 + a) * S_];

    float sx = 1.0f / (1.0f + expf(-tx));
    float sy = 1.0f / (1.0f + expf(-ty));
    float obj = 1.0f / (1.0f + expf(-to));

    float cf[C_];
    float mx = -1e30f;
#pragma unroll
    for (int c = 0; c < C_; c++) {
        cf[c] = p[(25 + a * C_ + c) * S_];
        mx = fmaxf(mx, cf[c]);
    }
    float sum = 0.0f;
#pragma unroll
    for (int c = 0; c < C_; c++) {
        cf[c] = expf(cf[c] - mx);
        sum += cf[c];
    }
    float osc = obj / sum;

    float imh = iminfo[2 * b + 0];
    float imw = iminfo[2 * b + 1];

    float bx = (sx + (float)wx) / 19.0f * imw;
    float by = (sy + (float)hy) / 19.0f * imh;
    float bw = expf(tw) * c_biases[2 * a] / 19.0f * imw;
    float bh = expf(th) * c_biases[2 * a + 1] / 19.0f * imh;

    reinterpret_cast<float4*>(out + PROB_ELEMS)[t] = make_float4(bx, by, bw, bh);

    float hw = bw * 0.5f, hh = bh * 0.5f;
    g_x1[t] = bx - hw;
    g_x2[t] = bx + hw;
    g_y1[t] = by - hh;
    g_y2[t] = by + hh;
    g_area[t] = bw * bh;

#pragma unroll
    for (int c = 0; c < C_; c++)
        g_scores[((size_t)b * C_ + c) * N_ + n] = cf[c] * osc;
}

// ---------------------------------------------------------------------------
// K2: suppression bitmask, one warp per 32x32 tile, upper triangle + ballot
// ---------------------------------------------------------------------------
__global__ __launch_bounds__(256) void k_mask() {
    int b = blockIdx.x;
    int warp = blockIdx.y * (blockDim.x >> 5) + (threadIdx.x >> 5);
    if (warp >= NTILE) return;
    int lane = threadIdx.x & 31;

    // map warp -> (rb, w) in upper triangle (w >= rb)
    int rb = 0, rem = warp;
    while (rem >= NW - rb) { rem -= NW - rb; rb++; }
    int w = rb + rem;

    int i = rb * 32 + lane;
    int gi = b * N_ + min(i, N_ - 1);
    float ix1 = g_x1[gi], iy1 = g_y1[gi], ix2 = g_x2[gi], iy2 = g_y2[gi];
    float ki = fmaf(0.45f, g_area[gi], 4.5e-10f);

    int jl = w * 32 + lane;
    int gj = b * N_ + min(jl, N_ - 1);
    float cx1 = g_x1[gj], cy1 = g_y1[gj], cx2 = g_x2[gj], cy2 = g_y2[gj];
    float ca = g_area[gj];

    unsigned bits = 0u, tbits = 0u;
    int jbase = w * 32;
#pragma unroll 8
    for (int jj = 0; jj < 32; jj++) {
        float jx1 = __shfl_sync(0xFFFFFFFFu, cx1, jj);
        float jy1 = __shfl_sync(0xFFFFFFFFu, cy1, jj);
        float jx2 = __shfl_sync(0xFFFFFFFFu, cx2, jj);
        float jy2 = __shfl_sync(0xFFFFFFFFu, cy2, jj);
        float ja  = __shfl_sync(0xFFFFFFFFu, ca, jj);
        float iw = fmaxf(fminf(ix2, jx2) - fmaxf(ix1, jx1), 0.0f);
        float ih = fmaxf(fminf(iy2, jy2) - fmaxf(iy1, jy1), 0.0f);
        float inter = iw * ih;
        // inter/(ai+aj-inter+1e-9) > 0.45  <=>  inter*1.45 > 0.45*(ai+aj+1e-9)
        bool pred = (inter * 1.45f > fmaf(0.45f, ja, ki)) && (i != jbase + jj);
        unsigned bal = __ballot_sync(0xFFFFFFFFu, pred);
        bits |= pred ? (1u << jj) : 0u;
        if (lane == jj) tbits = bal;
    }
    if (i < N_) g_mask[(size_t)(b * N_ + i) * MROW + w] = bits;
    if (w != rb && jl < N_) g_mask[(size_t)(b * N_ + jl) * MROW + rb] = tbits;
}

// ---------------------------------------------------------------------------
// K3: bitonic sort (descending) of 2048 packed keys per (b,c)
// key = (score_bits << 32) | (2047 - idx)   -> stable-tie matches argsort
// ---------------------------------------------------------------------------
__global__ __launch_bounds__(1024) void k_sort() {
    __shared__ unsigned long long sm[2048];
    int p = blockIdx.x;           // 0..319 = b*C + c
    int tid = threadIdx.x;
    const float* sc = g_scores + (size_t)p * N_;

#pragma unroll
    for (int q = 0; q < 2; q++) {
        int t = tid + q * 1024;
        unsigned long long key = 0ull;
        if (t < N_)
            key = ((unsigned long long)__float_as_uint(sc[t]) << 32) |
                  (unsigned long long)(2047u - (unsigned)t);
        sm[t] = key;
    }
    __syncthreads();

    for (int k = 2; k <= 2048; k <<= 1) {
        for (int j = k >> 1; j > 0; j >>= 1) {
            int i = ((tid & ~(j - 1)) << 1) | (tid & (j - 1));
            int pi = i | j;
            bool desc = ((i & k) == 0);
            unsigned long long a = sm[i], bb = sm[pi];
            if ((a < bb) == desc) { sm[i] = bb; sm[pi] = a; }
            __syncthreads();
        }
    }

    unsigned long long* op = g_order + (size_t)p * N_;
#pragma unroll
    for (int q = 0; q < 2; q++) {
        int t = tid + q * 1024;
        if (t < N_) op[t] = sm[t];
    }
}

// ---------------------------------------------------------------------------
// K4: greedy NMS, chunked 32-at-a-time, spill-free.
// Pass A: load q-column words, build sup[] via off-chain ballots.
// Serial recurrence: 32 x ~12cy scalar steps on uniform 'alive'.
// Pass B (after recurrence; valid because bit i of alive is final at step i):
//   stream member mask rows, accumulate keep-update with no register array.
// ---------------------------------------------------------------------------
__global__ __launch_bounds__(32, 1) void k_nms(float* __restrict__ out) {
    int p = blockIdx.x;                 // 0..319
    int b = p / C_, c = p - b * C_;
    int lane = threadIdx.x;

    const unsigned long long* __restrict__ ord = g_order + (size_t)p * N_;
    const unsigned* __restrict__ mbase = g_mask + (size_t)b * N_ * MROW;
    const uint2* __restrict__ mrow2 =
        reinterpret_cast<const uint2*>(g_mask) + (size_t)b * N_ * 32;
    float* __restrict__ op = out + (size_t)b * N_ * C_ + c;

    unsigned keepX = 0xFFFFFFFFu, keepY = 0xFFFFFFFFu;

    // per-lane key for chunk 0 (rank = lane)
    unsigned long long key = ord[lane];

    for (int ch = 0; ch < 57; ch++) {
        int rank = ch * 32 + lane;
        unsigned valid = (rank < N_) ? 1u : 0u;
        unsigned idxj = 2047u - (unsigned)key;          // per-lane box index
        unsigned wqj = idxj >> 5;                       // keep/mask word index
        unsigned bmask = 1u << (idxj & 31u);
        float scorej = __uint_as_float((unsigned)(key >> 32));
        unsigned kl = (unsigned)key;                    // low 32 for broadcast

        // prefetch next chunk's per-lane key (off-chain)
        int nrank = rank + 32;
        unsigned long long nkey = (nrank < N_) ? ord[nrank] : 0ull;

        // Pass A: member i's mask word at this lane's column -> q[i]
        unsigned q[32];
#pragma unroll
        for (int i = 0; i < 32; i++) {
            unsigned kli = __shfl_sync(0xFFFFFFFFu, kl, i);
            unsigned idxi = min(2047u - kli, (unsigned)(N_ - 1));
            q[i] = mbase[(size_t)idxi * 64u + wqj];
        }

        // gather this chunk's keep bits -> uniform 'alive' word
        unsigned vx = __shfl_sync(0xFFFFFFFFu, keepX, wqj >> 1);
        unsigned vy = __shfl_sync(0xFFFFFFFFu, keepY, wqj >> 1);
        unsigned wv = (wqj & 1u) ? vy : vx;
        unsigned alive =
            __ballot_sync(0xFFFFFFFFu, (wv & bmask) != 0u && valid);

        // suppression columns (ballots independent of the recurrence)
        unsigned sup[32];
#pragma unroll
        for (int i = 0; i < 32; i++) {
            unsigned bal = __ballot_sync(0xFFFFFFFFu, (q[i] & bmask) != 0u);
            sup[i] = bal & (0xFFFFFFFEu << i);
        }

        // serial greedy recurrence: uniform scalar, ~12 cy/step.
        // bit i of alive is FINAL after step i (sup only touches bits > i).
#pragma unroll
        for (int i = 0; i < 32; i++) {
            unsigned msk = (unsigned)((int)(alive << (31 - i)) >> 31);
            alive &= ~(sup[i] & msk);
        }

        // Pass B: accumulate keep-update from kept members' full rows.
        // No register array: each row load feeds two LOP3s immediately.
        unsigned cmbx = 0u, cmby = 0u;
#pragma unroll
        for (int i = 0; i < 32; i++) {
            unsigned kli = __shfl_sync(0xFFFFFFFFu, kl, i);
            unsigned idxi = min(2047u - kli, (unsigned)(N_ - 1));
            uint2 mm = mrow2[idxi * 32u + lane];
            unsigned msk = (unsigned)((int)(alive << (31 - i)) >> 31);
            cmbx |= mm.x & msk;
            cmby |= mm.y & msk;
        }
        keepX &= ~cmbx;
        keepY &= ~cmby;

        // per-lane predicated store (no divergent branch)
        float val = ((alive >> lane) & 1u) ? scorej : 0.0f;
        float* addr = op + (size_t)idxj * C_;
        asm volatile(
            "{ .reg .pred p; setp.ne.u32 p, %0, 0;\n"
            "  @p st.global.f32 [%1], %2; }"
            :: "r"(valid), "l"(addr), "f"(val) : "memory");

        key = nkey;
    }
}

// ---------------------------------------------------------------------------
extern "C" void kernel_launch(void* const* d_in, const int* in_sizes, int n_in,
                              void* d_out, int out_size) {
    const float* x = (const float*)d_in[0];
    const float* iminfo = (const float*)d_in[1];
    float* out = (float*)d_out;

    k_decode<<<(BN + 127) / 128, 128>>>(x, iminfo, out);

    dim3 gm(B_, (NTILE + 7) / 8);
    k_mask<<<gm, 256>>>();

    k_sort<<<B_ * C_, 1024>>>();

    k_nms<<<B_ * C_, 32>>>(out);
}

// round 5
// speedup vs baseline: 4.1194x; 1.0115x over previous
#include <cuda_runtime.h>
#include <cstdint>

#define B_ 16
#define A_ 5
#define C_ 20
#define HF 19
#define WF 19
#define S_ 361           // 19*19
#define N_ 1805          // A_*S_
#define BN 28880         // B_*N_
#define PROB_ELEMS 577600  // B_*N_*C_
#define NW 57            // ceil(1805/32)
#define MROW 64          // padded words per mask row (uint2 x 32)
#define NTILE 1653       // 57*58/2 upper-triangle tiles

__constant__ float c_biases[10] = {1.08f, 1.19f, 3.42f, 4.41f, 6.63f,
                                   11.38f, 9.42f, 5.11f, 16.62f, 10.52f};

// scratch (zero-initialized at module load; padding words of g_mask stay 0
// forever: k_mask only ever writes words 0..56 of each row)
__device__ float g_scores[PROB_ELEMS];                   // [b][c][n]
__device__ float g_x1[BN], g_y1[BN], g_x2[BN], g_y2[BN], g_area[BN];
__device__ unsigned g_mask[(size_t)B_ * N_ * MROW];      // [b][i][word]
__device__ unsigned long long g_order[(size_t)B_ * C_ * N_];

// ---------------------------------------------------------------------------
// K1: decode boxes + scores
// ---------------------------------------------------------------------------
__global__ __launch_bounds__(128) void k_decode(const float* __restrict__ x,
                                                const float* __restrict__ iminfo,
                                                float* __restrict__ out) {
    int t = blockIdx.x * blockDim.x + threadIdx.x;
    if (t >= BN) return;
    int b = t / N_, n = t - b * N_;
    int a = n / S_, s = n - a * S_;
    int hy = s / WF, wx = s - hy * WF;
    const float* p = x + (size_t)b * (125 * S_) + s;

    float tx = p[(2 * a) * S_];
    float ty = p[(2 * a + 1) * S_];
    float tw = p[(10 + 2 * a) * S_];
    float th = p[(11 + 2 * a) * S_];
    float to = p[(20 + a) * S_];

    float sx = 1.0f / (1.0f + expf(-tx));
    float sy = 1.0f / (1.0f + expf(-ty));
    float obj = 1.0f / (1.0f + expf(-to));

    float cf[C_];
    float mx = -1e30f;
#pragma unroll
    for (int c = 0; c < C_; c++) {
        cf[c] = p[(25 + a * C_ + c) * S_];
        mx = fmaxf(mx, cf[c]);
    }
    float sum = 0.0f;
#pragma unroll
    for (int c = 0; c < C_; c++) {
        cf[c] = expf(cf[c] - mx);
        sum += cf[c];
    }
    float osc = obj / sum;

    float imh = iminfo[2 * b + 0];
    float imw = iminfo[2 * b + 1];

    float bx = (sx + (float)wx) / 19.0f * imw;
    float by = (sy + (float)hy) / 19.0f * imh;
    float bw = expf(tw) * c_biases[2 * a] / 19.0f * imw;
    float bh = expf(th) * c_biases[2 * a + 1] / 19.0f * imh;

    reinterpret_cast<float4*>(out + PROB_ELEMS)[t] = make_float4(bx, by, bw, bh);

    float hw = bw * 0.5f, hh = bh * 0.5f;
    g_x1[t] = bx - hw;
    g_x2[t] = bx + hw;
    g_y1[t] = by - hh;
    g_y2[t] = by + hh;
    g_area[t] = bw * bh;

#pragma unroll
    for (int c = 0; c < C_; c++)
        g_scores[((size_t)b * C_ + c) * N_ + n] = cf[c] * osc;
}

// ---------------------------------------------------------------------------
// K2: suppression bitmask, one warp per 32x32 tile, upper triangle + ballot
// ---------------------------------------------------------------------------
__global__ __launch_bounds__(256) void k_mask() {
    int b = blockIdx.x;
    int warp = blockIdx.y * (blockDim.x >> 5) + (threadIdx.x >> 5);
    if (warp >= NTILE) return;
    int lane = threadIdx.x & 31;

    // map warp -> (rb, w) in upper triangle (w >= rb)
    int rb = 0, rem = warp;
    while (rem >= NW - rb) { rem -= NW - rb; rb++; }
    int w = rb + rem;

    int i = rb * 32 + lane;
    int gi = b * N_ + min(i, N_ - 1);
    float ix1 = g_x1[gi], iy1 = g_y1[gi], ix2 = g_x2[gi], iy2 = g_y2[gi];
    float ki = fmaf(0.45f, g_area[gi], 4.5e-10f);

    int jl = w * 32 + lane;
    int gj = b * N_ + min(jl, N_ - 1);
    float cx1 = g_x1[gj], cy1 = g_y1[gj], cx2 = g_x2[gj], cy2 = g_y2[gj];
    float ca = g_area[gj];

    unsigned bits = 0u, tbits = 0u;
    int jbase = w * 32;
#pragma unroll 8
    for (int jj = 0; jj < 32; jj++) {
        float jx1 = __shfl_sync(0xFFFFFFFFu, cx1, jj);
        float jy1 = __shfl_sync(0xFFFFFFFFu, cy1, jj);
        float jx2 = __shfl_sync(0xFFFFFFFFu, cx2, jj);
        float jy2 = __shfl_sync(0xFFFFFFFFu, cy2, jj);
        float ja  = __shfl_sync(0xFFFFFFFFu, ca, jj);
        float iw = fmaxf(fminf(ix2, jx2) - fmaxf(ix1, jx1), 0.0f);
        float ih = fmaxf(fminf(iy2, jy2) - fmaxf(iy1, jy1), 0.0f);
        float inter = iw * ih;
        // inter/(ai+aj-inter+1e-9) > 0.45  <=>  inter*1.45 > 0.45*(ai+aj+1e-9)
        bool pred = (inter * 1.45f > fmaf(0.45f, ja, ki)) && (i != jbase + jj);
        unsigned bal = __ballot_sync(0xFFFFFFFFu, pred);
        bits |= pred ? (1u << jj) : 0u;
        if (lane == jj) tbits = bal;
    }
    if (i < N_) g_mask[(size_t)(b * N_ + i) * MROW + w] = bits;
    if (w != rb && jl < N_) g_mask[(size_t)(b * N_ + jl) * MROW + rb] = tbits;
}

// ---------------------------------------------------------------------------
// K3: bitonic sort (descending) of 2048 packed keys per (b,c)
// key = (score_bits << 32) | (2047 - idx)   -> stable-tie matches argsort
// ---------------------------------------------------------------------------
__global__ __launch_bounds__(1024) void k_sort() {
    __shared__ unsigned long long sm[2048];
    int p = blockIdx.x;           // 0..319 = b*C + c
    int tid = threadIdx.x;
    const float* sc = g_scores + (size_t)p * N_;

#pragma unroll
    for (int q = 0; q < 2; q++) {
        int t = tid + q * 1024;
        unsigned long long key = 0ull;
        if (t < N_)
            key = ((unsigned long long)__float_as_uint(sc[t]) << 32) |
                  (unsigned long long)(2047u - (unsigned)t);
        sm[t] = key;
    }
    __syncthreads();

    for (int k = 2; k <= 2048; k <<= 1) {
        for (int j = k >> 1; j > 0; j >>= 1) {
            int i = ((tid & ~(j - 1)) << 1) | (tid & (j - 1));
            int pi = i | j;
            bool desc = ((i & k) == 0);
            unsigned long long a = sm[i], bb = sm[pi];
            if ((a < bb) == desc) { sm[i] = bb; sm[pi] = a; }
            __syncthreads();
        }
    }

    unsigned long long* op = g_order + (size_t)p * N_;
#pragma unroll
    for (int q = 0; q < 2; q++) {
        int t = tid + q * 1024;
        if (t < N_) op[t] = sm[t];
    }
}

// ---------------------------------------------------------------------------
// K4: greedy NMS, chunked 32-at-a-time, fully latency-hoisted.
// All loads (q columns for chunk ch+1, full rows m for chunk ch) are issued at
// chunk start; the 384-cy serial recurrence hides their latency. The serial
// cross-chunk chain is pure ALU/SHFL: keep-update -> gather -> ballot ->
// recurrence -> row-combine -> keep-update.
// ---------------------------------------------------------------------------
__global__ __launch_bounds__(32, 1) void k_nms(float* __restrict__ out) {
    int p = blockIdx.x;                 // 0..319
    int b = p / C_, c = p - b * C_;
    int lane = threadIdx.x;

    const unsigned long long* __restrict__ ord = g_order + (size_t)p * N_;
    const unsigned* __restrict__ mbase = g_mask + (size_t)b * N_ * MROW;
    const uint2* __restrict__ mrow2 =
        reinterpret_cast<const uint2*>(g_mask) + (size_t)b * N_ * 32;
    float* __restrict__ op = out + (size_t)b * N_ * C_ + c;

    unsigned keepX = 0xFFFFFFFFu, keepY = 0xFFFFFFFFu;

    // chunk-0 keys + q prefetch
    unsigned long long key = ord[lane];
    unsigned kl = (unsigned)key;
    unsigned idxj = 2047u - kl;
    unsigned wqj = idxj >> 5;
    unsigned bmask = 1u << (idxj & 31u);

    unsigned q[32];
#pragma unroll
    for (int i = 0; i < 32; i++) {
        unsigned kli = __shfl_sync(0xFFFFFFFFu, kl, i);
        unsigned idxi = min(2047u - kli, (unsigned)(N_ - 1));
        q[i] = mbase[(size_t)idxi * 64u + wqj];
    }

    for (int ch = 0; ch < 57; ch++) {
        int rank = ch * 32 + lane;
        unsigned valid = (rank < N_) ? 1u : 0u;
        float scorej = __uint_as_float((unsigned)(key >> 32));

        // next chunk's keys (off-chain)
        int nrank = rank + 32;
        unsigned long long nkey = (nrank < N_) ? ord[nrank] : 0ull;
        unsigned nkl = (unsigned)nkey;
        unsigned nidx = 2047u - nkl;
        unsigned nwq = nidx >> 5;

        // issue ALL loads up front (addresses independent of recurrence):
        //   m[i]  = member i's full row (2 words/lane) for the keep update
        //   qn[i] = next chunk's q-column words
        uint2 m[32];
        unsigned qn[32];
#pragma unroll
        for (int i = 0; i < 32; i++) {
            unsigned kli = __shfl_sync(0xFFFFFFFFu, kl, i);
            unsigned idxi = min(2047u - kli, (unsigned)(N_ - 1));
            m[i] = mrow2[idxi * 32u + lane];
            unsigned nkli = __shfl_sync(0xFFFFFFFFu, nkl, i);
            unsigned nidxi = min(2047u - nkli, (unsigned)(N_ - 1));
            qn[i] = mbase[(size_t)nidxi * 64u + nwq];
        }

        // gather this chunk's keep bits -> uniform 'alive' word
        unsigned vx = __shfl_sync(0xFFFFFFFFu, keepX, wqj >> 1);
        unsigned vy = __shfl_sync(0xFFFFFFFFu, keepY, wqj >> 1);
        unsigned wv = (wqj & 1u) ? vy : vx;
        unsigned alive =
            __ballot_sync(0xFFFFFFFFu, (wv & bmask) != 0u && valid);

        // suppression columns from register-resident q (loaded last chunk)
        unsigned sup[32];
#pragma unroll
        for (int i = 0; i < 32; i++) {
            unsigned bal = __ballot_sync(0xFFFFFFFFu, (q[i] & bmask) != 0u);
            sup[i] = bal & (0xFFFFFFFEu << i);
        }

        // serial greedy recurrence (bit i of alive final at step i;
        // alive & ~(sup & msk) is a single 3-input LOP3)
#pragma unroll
        for (int i = 0; i < 32; i++) {
            unsigned msk = (unsigned)((int)(alive << (31 - i)) >> 31);
            alive &= ~(sup[i] & msk);
        }

        // keep update from register-resident rows (pure ALU)
        unsigned cmbx = 0u, cmby = 0u;
#pragma unroll
        for (int i = 0; i < 32; i++) {
            unsigned msk = (unsigned)((int)(alive << (31 - i)) >> 31);
            cmbx |= m[i].x & msk;
            cmby |= m[i].y & msk;
        }
        keepX &= ~cmbx;
        keepY &= ~cmby;

        // per-lane predicated store (no divergent branch)
        float val = ((alive >> lane) & 1u) ? scorej : 0.0f;
        float* addr = op + (size_t)idxj * C_;
        asm volatile(
            "{ .reg .pred p; setp.ne.u32 p, %0, 0;\n"
            "  @p st.global.f32 [%1], %2; }"
            :: "r"(valid), "l"(addr), "f"(val) : "memory");

        // rotate chunk state
        key = nkey;
        kl = nkl;
        idxj = nidx;
        wqj = nwq;
        bmask = 1u << (nidx & 31u);
#pragma unroll
        for (int i = 0; i < 32; i++) q[i] = qn[i];
    }
}

// ---------------------------------------------------------------------------
extern "C" void kernel_launch(void* const* d_in, const int* in_sizes, int n_in,
                              void* d_out, int out_size) {
    const float* x = (const float*)d_in[0];
    const float* iminfo = (const float*)d_in[1];
    float* out = (float*)d_out;

    k_decode<<<(BN + 127) / 128, 128>>>(x, iminfo, out);

    dim3 gm(B_, (NTILE + 7) / 8);
    k_mask<<<gm, 256>>>();

    k_sort<<<B_ * C_, 1024>>>();

    k_nms<<<B_ * C_, 32>>>(out);
}